// round 5
// baseline (speedup 1.0000x reference)
#include <cuda_runtime.h>

// Critic_66511863546286 — folded attention critic, round 5.
// B=256, S=1024, H=256, feat dims = 2, 3 iterations.
// R5: pack along the H axis. Coefficients for (h, h+1) stored as 64-bit
// f32x2 pairs in shared (ulonglong2 -> one LDS.128 = two ready fma.rn.f32x2
// operands, zero packing MOVs). One sequence point per thread (1024-thread
// blocks), features duplicated into (x,x) pairs once outside the loop.
// MUFU.TANH is the intended binding pipe; everything else sits below it.

#define NB 256
#define NS 1024
#define NH 256
#define NHP 128  // h-pairs
#define K3 768
#define NITER 3
#define NFC 20

// Precomputed fused coefficients (natural scale).
__device__ float4 gABp[NH];  // (A0, A1, B0, B1) per h
__device__ float4 gCdv[NH];  // (C0, C1, d, v[h])
__device__ float2 gF[NFC];   // fc1_w · sw
__device__ float  gfb[NFC];  // fc1_w · sb + fc1_b

__device__ __forceinline__ float ex2_approx(float x) {
    float y; asm("ex2.approx.f32 %0, %1;" : "=f"(y) : "f"(x)); return y;
}
__device__ __forceinline__ float tanh_approx(float x) {
    float y; asm("tanh.approx.f32 %0, %1;" : "=f"(y) : "f"(x)); return y;
}
__device__ __forceinline__ unsigned long long pack2(float lo, float hi) {
    unsigned long long r;
    asm("mov.b64 %0, {%1, %2};" : "=l"(r) : "f"(lo), "f"(hi));
    return r;
}
__device__ __forceinline__ unsigned long long fma2(
    unsigned long long a, unsigned long long b, unsigned long long c) {
    unsigned long long r;
    asm("fma.rn.f32x2 %0, %1, %2, %3;" : "=l"(r) : "l"(a), "l"(b), "l"(c));
    return r;
}
__device__ __forceinline__ void unpack2(unsigned long long p, float& lo, float& hi) {
    asm("mov.b64 {%0, %1}, %2;" : "=f"(lo), "=f"(hi) : "l"(p));
}

// ---------------------------------------------------------------------------
// Precompute: fold W through the 1x1-conv encoders.
// Blocks 0..255 -> row h of A/B/C/d (+v).  Blocks 256..275 -> row j of F/fb.
// ---------------------------------------------------------------------------
__global__ void precompute_kernel(
    const float* __restrict__ sw, const float* __restrict__ sb,
    const float* __restrict__ dw, const float* __restrict__ db,
    const float* __restrict__ W,  const float* __restrict__ v,
    const float* __restrict__ fc1_w, const float* __restrict__ fc1_b)
{
    __shared__ float sred[8][8];
    int tid = threadIdx.x;
    int blk = blockIdx.x;
    int lane = tid & 31, w = tid >> 5;

    if (blk < NH) {
        int h = blk;
        float ws = W[h * K3 + tid];
        float wd = W[h * K3 + 256 + tid];
        float wc = W[h * K3 + 512 + tid];
        float s0 = sw[tid * 2 + 0], s1 = sw[tid * 2 + 1];
        float sbk = sb[tid];
        float p[7];
        p[0] = ws * s0;                             // A0
        p[1] = ws * s1;                             // A1
        p[2] = wd * dw[tid * 2 + 0];                // B0
        p[3] = wd * dw[tid * 2 + 1];                // B1
        p[4] = wc * s0;                             // C0
        p[5] = wc * s1;                             // C1
        p[6] = ws * sbk + wd * db[tid] + wc * sbk;  // d
        #pragma unroll
        for (int o = 16; o > 0; o >>= 1)
            #pragma unroll
            for (int i = 0; i < 7; i++)
                p[i] += __shfl_xor_sync(0xffffffffu, p[i], o);
        if (lane == 0) {
            #pragma unroll
            for (int i = 0; i < 7; i++) sred[w][i] = p[i];
        }
        __syncthreads();
        if (tid == 0) {
            float q[7];
            #pragma unroll
            for (int i = 0; i < 7; i++) {
                q[i] = 0.f;
                for (int ww = 0; ww < 8; ww++) q[i] += sred[ww][i];
            }
            gABp[h] = make_float4(q[0], q[1], q[2], q[3]);
            gCdv[h] = make_float4(q[4], q[5], q[6], v[h]);
        }
    } else {
        int j = blk - NH;  // 0..19
        float fw = fc1_w[j * NH + tid];
        float p0 = fw * sw[tid * 2 + 0];
        float p1 = fw * sw[tid * 2 + 1];
        float p2 = fw * sb[tid];
        #pragma unroll
        for (int o = 16; o > 0; o >>= 1) {
            p0 += __shfl_xor_sync(0xffffffffu, p0, o);
            p1 += __shfl_xor_sync(0xffffffffu, p1, o);
            p2 += __shfl_xor_sync(0xffffffffu, p2, o);
        }
        if (lane == 0) { sred[w][0] = p0; sred[w][1] = p1; sred[w][2] = p2; }
        __syncthreads();
        if (tid == 0) {
            float q0 = 0.f, q1 = 0.f, q2 = 0.f;
            for (int ww = 0; ww < 8; ww++) {
                q0 += sred[ww][0]; q1 += sred[ww][1]; q2 += sred[ww][2];
            }
            gF[j] = make_float2(q0, q1);
            gfb[j] = q2 + fc1_b[j];
        }
    }
}

// ---------------------------------------------------------------------------
// Main kernel: one block per batch element; 1024 threads; one point each.
// h processed in pairs via f32x2 with pair-native shared layout.
// ---------------------------------------------------------------------------
__global__ void __launch_bounds__(1024, 2)
attn_kernel(const float* __restrict__ stat, const float* __restrict__ dyn,
            const float* __restrict__ istate,
            const float* __restrict__ fc2_w, const float* __restrict__ fc2_b,
            float* __restrict__ out)
{
    __shared__ ulonglong2 sAB[NHP];   // {(A0h,A0h1), (A1h,A1h1)}
    __shared__ ulonglong2 sBB[NHP];   // {(B0h,B0h1), (B1h,B1h1)}
    __shared__ ulonglong2 sGV[NHP];   // {(gh,gh1),  (vh,vh1)} g rewritten/iter
    __shared__ float4 sCdv[NH];       // (C0,C1,d,v)
    __shared__ float sredM[32], sredP[32], sredX[32], sredY[32];
    __shared__ float bc[4];           // [0]=max [1]=sumP [2]=sum p*x0 [3]=sum p*x1

    const float LOG2E = 1.4426950408889634f;
    int b = blockIdx.x;
    int s = threadIdx.x;              // 0..1023
    int lane = s & 31, warp = s >> 5;

    float x0 = stat[b * 2 * NS + s];
    float x1 = stat[b * 2 * NS + NS + s];
    float y0 = dyn[b * 2 * NS + s];
    float y1 = dyn[b * 2 * NS + NS + s];
    unsigned long long x0p = pack2(x0, x0), x1p = pack2(x1, x1);
    unsigned long long y0p = pack2(y0, y0), y1p = pack2(y1, y1);

    if (s < NH) sCdv[s] = gCdv[s];
    if (s < NHP) {
        float4 pa = gABp[2 * s];
        float4 pb = gABp[2 * s + 1];
        sAB[s] = make_ulonglong2(pack2(pa.x, pb.x), pack2(pa.y, pb.y));
        sBB[s] = make_ulonglong2(pack2(pa.z, pb.z), pack2(pa.w, pb.w));
    }

    float z0 = istate[b * 2 + 0];
    float z1 = istate[b * 2 + 1];

    for (int it = 0; it < NITER; it++) {
        __syncthreads();
        if (s < NHP) {
            float4 ca = sCdv[2 * s];
            float4 cb = sCdv[2 * s + 1];
            float ga = fmaf(ca.x, z0, fmaf(ca.y, z1, ca.z));
            float gb = fmaf(cb.x, z0, fmaf(cb.y, z1, cb.z));
            sGV[s] = make_ulonglong2(pack2(ga, gb), pack2(ca.w, cb.w));
        }
        __syncthreads();

        // t = sum over h-pairs of (v,v') * tanh(A·x + B·y + (g,g'))
        unsigned long long acc = 0ull;    // packed (0.f, 0.f)
        #pragma unroll 4
        for (int k = 0; k < NHP; k++) {
            ulonglong2 a2 = sAB[k];       // LDS.128
            ulonglong2 b2 = sBB[k];       // LDS.128
            ulonglong2 gv = sGV[k];       // LDS.128
            unsigned long long arg = fma2(a2.x, x0p, gv.x);
            arg = fma2(a2.y, x1p, arg);
            arg = fma2(b2.x, y0p, arg);
            arg = fma2(b2.y, y1p, arg);
            float al, ah; unpack2(arg, al, ah);
            float thl = tanh_approx(al);
            float thh = tanh_approx(ah);
            acc = fma2(gv.y, pack2(thl, thh), acc);
        }
        float ta, tb; unpack2(acc, ta, tb);
        float t = ta + tb;

        // block max over S=1024
        float m = t;
        #pragma unroll
        for (int o = 16; o > 0; o >>= 1)
            m = fmaxf(m, __shfl_xor_sync(0xffffffffu, m, o));
        if (lane == 0) sredM[warp] = m;
        __syncthreads();
        if (s < 32) {
            float mm = sredM[s];
            #pragma unroll
            for (int o = 16; o > 0; o >>= 1)
                mm = fmaxf(mm, __shfl_xor_sync(0xffffffffu, mm, o));
            if (s == 0) bc[0] = mm;
        }
        __syncthreads();
        float M = bc[0];

        // softmax weight + weighted feature sums
        float p = ex2_approx((t - M) * LOG2E);
        float a = p, bx = p * x0, by = p * x1;
        #pragma unroll
        for (int o = 16; o > 0; o >>= 1) {
            a  += __shfl_xor_sync(0xffffffffu, a,  o);
            bx += __shfl_xor_sync(0xffffffffu, bx, o);
            by += __shfl_xor_sync(0xffffffffu, by, o);
        }
        if (lane == 0) { sredP[warp] = a; sredX[warp] = bx; sredY[warp] = by; }
        __syncthreads();
        if (s < 32) {
            float aa = sredP[s], xx = sredX[s], yy = sredY[s];
            #pragma unroll
            for (int o = 16; o > 0; o >>= 1) {
                aa += __shfl_xor_sync(0xffffffffu, aa, o);
                xx += __shfl_xor_sync(0xffffffffu, xx, o);
                yy += __shfl_xor_sync(0xffffffffu, yy, o);
            }
            if (s == 0) { bc[1] = aa; bc[2] = xx; bc[3] = yy; }
        }
        __syncthreads();
        float inv = 1.f / bc[1];
        z0 = bc[2] * inv;   // xbar0
        z1 = bc[3] * inv;   // xbar1
    }

    // Output MLP (folded through sw)
    if (s == 0) {
        float o = fc2_b[0];
        #pragma unroll
        for (int j = 0; j < NFC; j++) {
            float hv = fmaf(gF[j].x, z0, fmaf(gF[j].y, z1, gfb[j]));
            hv = fmaxf(hv, 0.f);
            o = fmaf(fc2_w[j], hv, o);
        }
        out[b] = o;
    }
}

extern "C" void kernel_launch(void* const* d_in, const int* in_sizes, int n_in,
                              void* d_out, int out_size)
{
    const float* stat   = (const float*)d_in[0];   // [256, 2, 1024]
    const float* dyn    = (const float*)d_in[1];   // [256, 2, 1024]
    const float* istate = (const float*)d_in[2];   // [256, 2]
    const float* sw     = (const float*)d_in[3];   // [256, 2]
    const float* sb     = (const float*)d_in[4];   // [256]
    const float* dw     = (const float*)d_in[5];   // [256, 2]
    const float* db     = (const float*)d_in[6];   // [256]
    const float* v      = (const float*)d_in[7];   // [1, 256]
    const float* W      = (const float*)d_in[8];   // [256, 768]
    const float* fc1_w  = (const float*)d_in[9];   // [20, 256]
    const float* fc1_b  = (const float*)d_in[10];  // [20]
    const float* fc2_w  = (const float*)d_in[11];  // [1, 20]
    const float* fc2_b  = (const float*)d_in[12];  // [1]
    float* out = (float*)d_out;                    // [256, 1]

    precompute_kernel<<<NH + NFC, 256>>>(sw, sb, dw, db, W, v, fc1_w, fc1_b);
    attn_kernel<<<NB, NS>>>(stat, dyn, istate, fc2_w, fc2_b, out);
}

// round 6
// speedup vs baseline: 1.3332x; 1.3332x over previous
#include <cuda_runtime.h>

// Critic_66511863546286 — folded attention critic, round 6.
// B=256, S=1024, H=256, feat dims = 2, 3 iterations.
// R6 = R5's h-pair f32x2 layout (coefficient pairs ready for fma.rn.f32x2
// straight from LDS.128, zero packing) + R3's 2 points/thread (each
// coefficient load amortized over 2 points -> R3's wavefront count).
// Intended binder: MUFU.TANH; FMA/LDS/issue all sized below it.

#define NB 256
#define NS 1024
#define NH 256
#define NHP 128  // h-pairs
#define K3 768
#define NITER 3
#define NFC 20
#define BT 512   // threads/block; thread t owns points t (lo) and t+512 (hi)

// Precomputed fused coefficients (natural scale).
__device__ float4 gABp[NH];  // (A0, A1, B0, B1) per h
__device__ float4 gCdv[NH];  // (C0, C1, d, v[h])
__device__ float2 gF[NFC];   // fc1_w · sw
__device__ float  gfb[NFC];  // fc1_w · sb + fc1_b

__device__ __forceinline__ float ex2_approx(float x) {
    float y; asm("ex2.approx.f32 %0, %1;" : "=f"(y) : "f"(x)); return y;
}
__device__ __forceinline__ float tanh_approx(float x) {
    float y; asm("tanh.approx.f32 %0, %1;" : "=f"(y) : "f"(x)); return y;
}
__device__ __forceinline__ unsigned long long pack2(float lo, float hi) {
    unsigned long long r;
    asm("mov.b64 %0, {%1, %2};" : "=l"(r) : "f"(lo), "f"(hi));
    return r;
}
__device__ __forceinline__ unsigned long long fma2(
    unsigned long long a, unsigned long long b, unsigned long long c) {
    unsigned long long r;
    asm("fma.rn.f32x2 %0, %1, %2, %3;" : "=l"(r) : "l"(a), "l"(b), "l"(c));
    return r;
}
__device__ __forceinline__ void unpack2(unsigned long long p, float& lo, float& hi) {
    asm("mov.b64 {%0, %1}, %2;" : "=f"(lo), "=f"(hi) : "l"(p));
}

// ---------------------------------------------------------------------------
// Precompute: fold W through the 1x1-conv encoders.
// Blocks 0..255 -> row h of A/B/C/d (+v).  Blocks 256..275 -> row j of F/fb.
// ---------------------------------------------------------------------------
__global__ void precompute_kernel(
    const float* __restrict__ sw, const float* __restrict__ sb,
    const float* __restrict__ dw, const float* __restrict__ db,
    const float* __restrict__ W,  const float* __restrict__ v,
    const float* __restrict__ fc1_w, const float* __restrict__ fc1_b)
{
    __shared__ float sred[8][8];
    int tid = threadIdx.x;
    int blk = blockIdx.x;
    int lane = tid & 31, w = tid >> 5;

    if (blk < NH) {
        int h = blk;
        float ws = W[h * K3 + tid];
        float wd = W[h * K3 + 256 + tid];
        float wc = W[h * K3 + 512 + tid];
        float s0 = sw[tid * 2 + 0], s1 = sw[tid * 2 + 1];
        float sbk = sb[tid];
        float p[7];
        p[0] = ws * s0;                             // A0
        p[1] = ws * s1;                             // A1
        p[2] = wd * dw[tid * 2 + 0];                // B0
        p[3] = wd * dw[tid * 2 + 1];                // B1
        p[4] = wc * s0;                             // C0
        p[5] = wc * s1;                             // C1
        p[6] = ws * sbk + wd * db[tid] + wc * sbk;  // d
        #pragma unroll
        for (int o = 16; o > 0; o >>= 1)
            #pragma unroll
            for (int i = 0; i < 7; i++)
                p[i] += __shfl_xor_sync(0xffffffffu, p[i], o);
        if (lane == 0) {
            #pragma unroll
            for (int i = 0; i < 7; i++) sred[w][i] = p[i];
        }
        __syncthreads();
        if (tid == 0) {
            float q[7];
            #pragma unroll
            for (int i = 0; i < 7; i++) {
                q[i] = 0.f;
                for (int ww = 0; ww < 8; ww++) q[i] += sred[ww][i];
            }
            gABp[h] = make_float4(q[0], q[1], q[2], q[3]);
            gCdv[h] = make_float4(q[4], q[5], q[6], v[h]);
        }
    } else {
        int j = blk - NH;  // 0..19
        float fw = fc1_w[j * NH + tid];
        float p0 = fw * sw[tid * 2 + 0];
        float p1 = fw * sw[tid * 2 + 1];
        float p2 = fw * sb[tid];
        #pragma unroll
        for (int o = 16; o > 0; o >>= 1) {
            p0 += __shfl_xor_sync(0xffffffffu, p0, o);
            p1 += __shfl_xor_sync(0xffffffffu, p1, o);
            p2 += __shfl_xor_sync(0xffffffffu, p2, o);
        }
        if (lane == 0) { sred[w][0] = p0; sred[w][1] = p1; sred[w][2] = p2; }
        __syncthreads();
        if (tid == 0) {
            float q0 = 0.f, q1 = 0.f, q2 = 0.f;
            for (int ww = 0; ww < 8; ww++) {
                q0 += sred[ww][0]; q1 += sred[ww][1]; q2 += sred[ww][2];
            }
            gF[j] = make_float2(q0, q1);
            gfb[j] = q2 + fc1_b[j];
        }
    }
}

// ---------------------------------------------------------------------------
// Main kernel: one block per batch element; 512 threads; thread t owns
// points t (lo) and t+512 (hi); h processed in f32x2 pairs.
// ---------------------------------------------------------------------------
__global__ void __launch_bounds__(BT, 2)
attn_kernel(const float* __restrict__ stat, const float* __restrict__ dyn,
            const float* __restrict__ istate,
            const float* __restrict__ fc2_w, const float* __restrict__ fc2_b,
            float* __restrict__ out)
{
    __shared__ ulonglong2 sAB[NHP];   // {(A0h,A0h1), (A1h,A1h1)}
    __shared__ ulonglong2 sBB[NHP];   // {(B0h,B0h1), (B1h,B1h1)}
    __shared__ ulonglong2 sGV[NHP];   // {(gh,gh1),  (vh,vh1)} g rewritten/iter
    __shared__ float4 sCdv[NH];       // (C0,C1,d,v)
    __shared__ float sredM[16], sredP[16], sredX[16], sredY[16];
    __shared__ float bc[4];           // [0]=max [1]=sumP [2]=sum p*x0 [3]=sum p*x1

    const float LOG2E = 1.4426950408889634f;
    int b = blockIdx.x;
    int s = threadIdx.x;              // 0..511
    int lane = s & 31, warp = s >> 5;

    // features for points s (lo) and s+512 (hi), each duplicated into f32x2
    float x0l = stat[b * 2 * NS + s],      x0h = stat[b * 2 * NS + s + BT];
    float x1l = stat[b * 2 * NS + NS + s], x1h = stat[b * 2 * NS + NS + s + BT];
    float y0l = dyn[b * 2 * NS + s],       y0h = dyn[b * 2 * NS + s + BT];
    float y1l = dyn[b * 2 * NS + NS + s],  y1h = dyn[b * 2 * NS + NS + s + BT];
    unsigned long long x0lp = pack2(x0l, x0l), x0hp = pack2(x0h, x0h);
    unsigned long long x1lp = pack2(x1l, x1l), x1hp = pack2(x1h, x1h);
    unsigned long long y0lp = pack2(y0l, y0l), y0hp = pack2(y0h, y0h);
    unsigned long long y1lp = pack2(y1l, y1l), y1hp = pack2(y1h, y1h);

    if (s < NH) sCdv[s] = gCdv[s];
    if (s < NHP) {
        float4 pa = gABp[2 * s];
        float4 pb = gABp[2 * s + 1];
        sAB[s] = make_ulonglong2(pack2(pa.x, pb.x), pack2(pa.y, pb.y));
        sBB[s] = make_ulonglong2(pack2(pa.z, pb.z), pack2(pa.w, pb.w));
    }

    float z0 = istate[b * 2 + 0];
    float z1 = istate[b * 2 + 1];

    for (int it = 0; it < NITER; it++) {
        __syncthreads();
        if (s < NHP) {
            float4 ca = sCdv[2 * s];
            float4 cb = sCdv[2 * s + 1];
            float ga = fmaf(ca.x, z0, fmaf(ca.y, z1, ca.z));
            float gb = fmaf(cb.x, z0, fmaf(cb.y, z1, cb.z));
            sGV[s] = make_ulonglong2(pack2(ga, gb), pack2(ca.w, cb.w));
        }
        __syncthreads();

        // per point: t = sum over h-pairs of (v,v') * tanh(A·x + B·y + (g,g'))
        unsigned long long accl = 0ull, acch = 0ull;   // packed (0.f,0.f)
        #pragma unroll 4
        for (int k = 0; k < NHP; k++) {
            ulonglong2 a2 = sAB[k];      // LDS.128
            ulonglong2 b2 = sBB[k];      // LDS.128
            ulonglong2 gv = sGV[k];      // LDS.128

            unsigned long long argl = fma2(a2.x, x0lp, gv.x);
            argl = fma2(a2.y, x1lp, argl);
            argl = fma2(b2.x, y0lp, argl);
            argl = fma2(b2.y, y1lp, argl);

            unsigned long long argh = fma2(a2.x, x0hp, gv.x);
            argh = fma2(a2.y, x1hp, argh);
            argh = fma2(b2.x, y0hp, argh);
            argh = fma2(b2.y, y1hp, argh);

            float l0, l1, h0, h1;
            unpack2(argl, l0, l1);
            unpack2(argh, h0, h1);
            accl = fma2(gv.y, pack2(tanh_approx(l0), tanh_approx(l1)), accl);
            acch = fma2(gv.y, pack2(tanh_approx(h0), tanh_approx(h1)), acch);
        }
        float ta, tb, tc, td;
        unpack2(accl, ta, tb);
        unpack2(acch, tc, td);
        float t0 = ta + tb;   // score of point s
        float t1 = tc + td;   // score of point s+512

        // block max over all 1024 points
        float m = fmaxf(t0, t1);
        #pragma unroll
        for (int o = 16; o > 0; o >>= 1)
            m = fmaxf(m, __shfl_xor_sync(0xffffffffu, m, o));
        if (lane == 0) sredM[warp] = m;
        __syncthreads();
        if (s < 16) {
            float mm = sredM[s];
            #pragma unroll
            for (int o = 8; o > 0; o >>= 1)
                mm = fmaxf(mm, __shfl_xor_sync(0xffffu, mm, o));
            if (s == 0) bc[0] = mm;
        }
        __syncthreads();
        float M = bc[0];

        // softmax weights + weighted feature sums
        float p0 = ex2_approx((t0 - M) * LOG2E);
        float p1 = ex2_approx((t1 - M) * LOG2E);
        float a  = p0 + p1;
        float bx = fmaf(p0, x0l, p1 * x0h);
        float by = fmaf(p0, x1l, p1 * x1h);
        #pragma unroll
        for (int o = 16; o > 0; o >>= 1) {
            a  += __shfl_xor_sync(0xffffffffu, a,  o);
            bx += __shfl_xor_sync(0xffffffffu, bx, o);
            by += __shfl_xor_sync(0xffffffffu, by, o);
        }
        if (lane == 0) { sredP[warp] = a; sredX[warp] = bx; sredY[warp] = by; }
        __syncthreads();
        if (s < 16) {
            float aa = sredP[s], xx = sredX[s], yy = sredY[s];
            #pragma unroll
            for (int o = 8; o > 0; o >>= 1) {
                aa += __shfl_xor_sync(0xffffu, aa, o);
                xx += __shfl_xor_sync(0xffffu, xx, o);
                yy += __shfl_xor_sync(0xffffu, yy, o);
            }
            if (s == 0) { bc[1] = aa; bc[2] = xx; bc[3] = yy; }
        }
        __syncthreads();
        float inv = 1.f / bc[1];
        z0 = bc[2] * inv;   // xbar0
        z1 = bc[3] * inv;   // xbar1
    }

    // Output MLP (folded through sw)
    if (s == 0) {
        float o = fc2_b[0];
        #pragma unroll
        for (int j = 0; j < NFC; j++) {
            float hv = fmaf(gF[j].x, z0, fmaf(gF[j].y, z1, gfb[j]));
            hv = fmaxf(hv, 0.f);
            o = fmaf(fc2_w[j], hv, o);
        }
        out[b] = o;
    }
}

extern "C" void kernel_launch(void* const* d_in, const int* in_sizes, int n_in,
                              void* d_out, int out_size)
{
    const float* stat   = (const float*)d_in[0];   // [256, 2, 1024]
    const float* dyn    = (const float*)d_in[1];   // [256, 2, 1024]
    const float* istate = (const float*)d_in[2];   // [256, 2]
    const float* sw     = (const float*)d_in[3];   // [256, 2]
    const float* sb     = (const float*)d_in[4];   // [256]
    const float* dw     = (const float*)d_in[5];   // [256, 2]
    const float* db     = (const float*)d_in[6];   // [256]
    const float* v      = (const float*)d_in[7];   // [1, 256]
    const float* W      = (const float*)d_in[8];   // [256, 768]
    const float* fc1_w  = (const float*)d_in[9];   // [20, 256]
    const float* fc1_b  = (const float*)d_in[10];  // [20]
    const float* fc2_w  = (const float*)d_in[11];  // [1, 20]
    const float* fc2_b  = (const float*)d_in[12];  // [1]
    float* out = (float*)d_out;                    // [256, 1]

    precompute_kernel<<<NH + NFC, 256>>>(sw, sb, dw, db, W, v, fc1_w, fc1_b);
    attn_kernel<<<NB, BT>>>(stat, dyn, istate, fc2_w, fc2_b, out);
}